// round 13
// baseline (speedup 1.0000x reference)
#include <cuda_runtime.h>
#include <cuda_bf16.h>
#include <mma.h>
#include <float.h>
#include <math.h>
#include <stdint.h>

using namespace nvcuda;

// Problem constants (fixed by the dataset)
#define NN 20000
#define NNP 20096          // 157 * 128 : M padded to a whole tile grid
#define EE 320000
#define ET (NN + EE)       // edges incl. self loops = 340000
#define GG 32

// ------------------------------------------------------------------
// Scratch (device globals; no runtime allocation allowed)
// ------------------------------------------------------------------
__device__ float g_h0[(size_t)NNP * 768];    // GEMM1 out (padded rows garbage, unread)
__device__ float g_hh[(size_t)NNP * 1024];   // GEMM2/3/4 out
__device__ float g_x1[NN * 1024];
__device__ float g_x3[NN * 256];
__device__ float g_es[NN * 4];
__device__ float g_ed[NN * 4];
__device__ float g_alpha[(size_t)ET * 4];
__device__ int   g_counts[NN];
__device__ int   g_offs[NN + 1];
__device__ int   g_cursor[NN];
__device__ int   g_csr_src[ET];
__device__ float g_ssum[GG * 256];
__device__ float g_smax[GG * 256];
__device__ int   g_cnt[GG];
__device__ float g_pooled[GG * 768];
__device__ float g_hidden[GG * 128];
__device__ float g_wt[1024 * 1024];                       // transposed weights (fp32)
__device__ __nv_bfloat16 g_ahi[(size_t)NNP * 1024];       // split A (hi)
__device__ __nv_bfloat16 g_alo[(size_t)NNP * 1024];       // split A (lo)
__device__ __nv_bfloat16 g_bhi[1024 * 1024];              // split Wt (hi)
__device__ __nv_bfloat16 g_blo[1024 * 1024];              // split Wt (lo)

__device__ __forceinline__ float lrelu02(float x) { return x > 0.f ? x : 0.2f * x; }
__device__ __forceinline__ float eluf(float x)    { return x > 0.f ? x : expm1f(x); }

__device__ __forceinline__ uint32_t smem_u32(const void* p) {
    uint32_t a;
    asm("{ .reg .u64 t; cvta.to.shared.u64 t, %1; cvt.u32.u64 %0, t; }" : "=r"(a) : "l"(p));
    return a;
}

// cp.async (Ampere-era PTX; compiles for plain sm_103)
#define CP_ASYNC16(dst_u32, src_ptr) \
    asm volatile("cp.async.cg.shared.global [%0], [%1], 16;" :: "r"(dst_u32), "l"(src_ptr))
#define CP_COMMIT() asm volatile("cp.async.commit_group;")
#define CP_WAIT1()  asm volatile("cp.async.wait_group 1;")
#define CP_WAIT0()  asm volatile("cp.async.wait_group 0;")

__device__ __forceinline__ uint32_t pack2(float x0, float x1) {
    __nv_bfloat162 h = __floats2bfloat162_rn(x0, x1);
    return *(uint32_t*)&h;
}
__device__ __forceinline__ float bf16hi(float x) {
    return __bfloat162float(__float2bfloat16_rn(x));
}

// ------------------------------------------------------------------
// 32x32 tiled transpose: Wt[N][K] = W[K][N]
// ------------------------------------------------------------------
__global__ void transpose_kernel(const float* __restrict__ W, float* __restrict__ Wt,
                                 int K, int N) {
    __shared__ float t[32][33];
    int n0 = blockIdx.x * 32, k0 = blockIdx.y * 32;
    for (int j = threadIdx.y; j < 32; j += 8)
        t[j][threadIdx.x] = W[(size_t)(k0 + j) * N + n0 + threadIdx.x];
    __syncthreads();
    for (int j = threadIdx.y; j < 32; j += 8)
        Wt[(size_t)(n0 + j) * K + k0 + threadIdx.x] = t[threadIdx.x][j];
}

// ------------------------------------------------------------------
// Split fp32 -> (hi, lo) bf16 arrays over total elements (8 per thread).
// ------------------------------------------------------------------
__global__ void split_kernel(const float* __restrict__ A,
                             __nv_bfloat16* __restrict__ hi,
                             __nv_bfloat16* __restrict__ lo,
                             size_t total) {
    size_t i8 = ((size_t)blockIdx.x * blockDim.x + threadIdx.x) * 8;
    if (i8 >= total) return;
    float4 a = *(const float4*)(A + i8);
    float4 b = *(const float4*)(A + i8 + 4);
    float h0 = bf16hi(a.x), h1 = bf16hi(a.y), h2 = bf16hi(a.z), h3 = bf16hi(a.w);
    float h4 = bf16hi(b.x), h5 = bf16hi(b.y), h6 = bf16hi(b.z), h7 = bf16hi(b.w);
    uint4 hv, lv;
    hv.x = pack2(a.x, a.y); hv.y = pack2(a.z, a.w);
    hv.z = pack2(b.x, b.y); hv.w = pack2(b.z, b.w);
    lv.x = pack2(a.x - h0, a.y - h1); lv.y = pack2(a.z - h2, a.w - h3);
    lv.z = pack2(b.x - h4, b.y - h5); lv.w = pack2(b.z - h6, b.w - h7);
    *(uint4*)(hi + i8) = hv;
    *(uint4*)(lo + i8) = lv;
}

// bias + ELU + split (GEMM1 epilogue; fp32 result is NOT kept)
__global__ void bias_elu_split_kernel(const float* __restrict__ h,
                                      const float* __restrict__ b,
                                      __nv_bfloat16* __restrict__ hi,
                                      __nv_bfloat16* __restrict__ lo, int D) {
    size_t i8 = ((size_t)blockIdx.x * blockDim.x + threadIdx.x) * 8;
    if (i8 >= (size_t)NN * D) return;
    int c0 = (int)(i8 % (size_t)D);
    float v[8];
#pragma unroll
    for (int j = 0; j < 8; j++) v[j] = eluf(h[i8 + j] + b[c0 + j]);
    uint4 hv, lv;
    float t0 = bf16hi(v[0]), t1 = bf16hi(v[1]), t2 = bf16hi(v[2]), t3 = bf16hi(v[3]);
    float t4 = bf16hi(v[4]), t5 = bf16hi(v[5]), t6 = bf16hi(v[6]), t7 = bf16hi(v[7]);
    hv.x = pack2(v[0], v[1]); hv.y = pack2(v[2], v[3]);
    hv.z = pack2(v[4], v[5]); hv.w = pack2(v[6], v[7]);
    lv.x = pack2(v[0] - t0, v[1] - t1); lv.y = pack2(v[2] - t2, v[3] - t3);
    lv.z = pack2(v[4] - t4, v[5] - t5); lv.w = pack2(v[6] - t6, v[7] - t7);
    *(uint4*)(hi + i8) = hv;
    *(uint4*)(lo + i8) = lv;
}

// ------------------------------------------------------------------
// WMMA split-bf16 GEMM (cp.async double-buffered) — unchanged (validated).
// ------------------------------------------------------------------
#define PITCH 40
#define ARR_B (128 * PITCH * 2)
#define STAGE_B (4 * ARR_B)
#define GEMM_SMEM (2 * STAGE_B)

__global__ __launch_bounds__(256) void wmma_gemm_kernel(
    const __nv_bfloat16* __restrict__ Ahi, const __nv_bfloat16* __restrict__ Alo,
    const __nv_bfloat16* __restrict__ Bhi, const __nv_bfloat16* __restrict__ Blo,
    float* __restrict__ C, int N, int K)
{
    extern __shared__ char smem[];
    const uint32_t sbase = smem_u32(smem);

    const int tid = threadIdx.x;
    const int wid = tid >> 5;
    const int bm = blockIdx.y * 128, bn = blockIdx.x * 128;
    const int wm = (wid >> 1) * 32, wn = (wid & 1) * 64;

    wmma::fragment<wmma::accumulator, 16, 16, 16, float> acc[2][4];
#pragma unroll
    for (int mt = 0; mt < 2; mt++)
#pragma unroll
        for (int nt = 0; nt < 4; nt++) wmma::fill_fragment(acc[mt][nt], 0.f);

    const int lr0 = tid >> 2;
    const int seg = (tid & 3) * 8;
    const __nv_bfloat16* gA[4] = {
        Ahi + (size_t)(bm + lr0) * K + seg, Alo + (size_t)(bm + lr0) * K + seg,
        Bhi + (size_t)(bn + lr0) * K + seg, Blo + (size_t)(bn + lr0) * K + seg };
    const size_t rowStride64 = (size_t)64 * K;
    const uint32_t dOff = (uint32_t)(lr0 * (PITCH * 2) + seg * 2);

    const int nch = K >> 5;

    {
#pragma unroll
        for (int a = 0; a < 4; a++) {
            uint32_t dst = sbase + a * ARR_B + dOff;
            CP_ASYNC16(dst, gA[a]);
            CP_ASYNC16(dst + 64 * (PITCH * 2), gA[a] + rowStride64);
        }
        CP_COMMIT();
    }

    for (int c = 0; c < nch; c++) {
        if (c + 1 < nch) {
            const int k0 = (c + 1) << 5;
            const uint32_t st = sbase + ((c + 1) & 1) * STAGE_B;
#pragma unroll
            for (int a = 0; a < 4; a++) {
                uint32_t dst = st + a * ARR_B + dOff;
                CP_ASYNC16(dst, gA[a] + k0);
                CP_ASYNC16(dst + 64 * (PITCH * 2), gA[a] + k0 + rowStride64);
            }
            CP_COMMIT();
            CP_WAIT1();
        } else {
            CP_WAIT0();
        }
        __syncthreads();

        const char* st = smem + (c & 1) * STAGE_B;
        const __nv_bfloat16* sAhi = (const __nv_bfloat16*)(st);
        const __nv_bfloat16* sAlo = (const __nv_bfloat16*)(st + ARR_B);
        const __nv_bfloat16* sBhi = (const __nv_bfloat16*)(st + 2 * ARR_B);
        const __nv_bfloat16* sBlo = (const __nv_bfloat16*)(st + 3 * ARR_B);

#pragma unroll
        for (int ks = 0; ks < 2; ks++) {
            wmma::fragment<wmma::matrix_a, 16, 16, 16, __nv_bfloat16, wmma::row_major> fahi[2], falo[2];
#pragma unroll
            for (int mt = 0; mt < 2; mt++) {
                wmma::load_matrix_sync(fahi[mt], sAhi + (wm + mt * 16) * PITCH + ks * 16, PITCH);
                wmma::load_matrix_sync(falo[mt], sAlo + (wm + mt * 16) * PITCH + ks * 16, PITCH);
            }
#pragma unroll
            for (int nt = 0; nt < 4; nt++) {
                wmma::fragment<wmma::matrix_b, 16, 16, 16, __nv_bfloat16, wmma::col_major> fbhi, fblo;
                wmma::load_matrix_sync(fbhi, sBhi + (wn + nt * 16) * PITCH + ks * 16, PITCH);
                wmma::load_matrix_sync(fblo, sBlo + (wn + nt * 16) * PITCH + ks * 16, PITCH);
#pragma unroll
                for (int mt = 0; mt < 2; mt++) {
                    wmma::mma_sync(acc[mt][nt], fahi[mt], fbhi, acc[mt][nt]);
                    wmma::mma_sync(acc[mt][nt], fahi[mt], fblo, acc[mt][nt]);
                    wmma::mma_sync(acc[mt][nt], falo[mt], fbhi, acc[mt][nt]);
                }
            }
        }
        __syncthreads();
    }

#pragma unroll
    for (int mt = 0; mt < 2; mt++)
#pragma unroll
        for (int nt = 0; nt < 4; nt++)
            wmma::store_matrix_sync(C + (size_t)(bm + wm + mt * 16) * N + bn + wn + nt * 16,
                                    acc[mt][nt], N, wmma::mem_row_major);
}

// ------------------------------------------------------------------
// CSR build (dst-grouped)
// ------------------------------------------------------------------
__global__ void zero_int_kernel(int* p, int n) {
    int i = blockIdx.x * blockDim.x + threadIdx.x;
    if (i < n) p[i] = 0;
}

__global__ void count_kernel(const int* __restrict__ ei) {
    int e = blockIdx.x * blockDim.x + threadIdx.x;
    if (e >= ET) return;
    int d = (e < EE) ? ei[EE + e] : (e - EE);
    atomicAdd(&g_counts[d], 1);
}

__global__ void scan_kernel() {
    __shared__ int sums[1024];
    const int tid = threadIdx.x;
    const int CH = (NN + 1023) / 1024;
    int beg = tid * CH;
    int end = beg + CH; if (end > NN) end = NN;
    int s = 0;
    for (int i = beg; i < end; i++) s += g_counts[i];
    sums[tid] = s;
    __syncthreads();
    for (int o = 1; o < 1024; o <<= 1) {
        int v = (tid >= o) ? sums[tid - o] : 0;
        __syncthreads();
        sums[tid] += v;
        __syncthreads();
    }
    int run = (tid > 0) ? sums[tid - 1] : 0;
    for (int i = beg; i < end; i++) { g_offs[i] = run; run += g_counts[i]; }
    if (tid == 1023) g_offs[NN] = sums[1023];
}

__global__ void fill_kernel(const int* __restrict__ ei) {
    int e = blockIdx.x * blockDim.x + threadIdx.x;
    if (e >= ET) return;
    int s, d;
    if (e < EE) { s = ei[e]; d = ei[EE + e]; }
    else        { s = e - EE; d = e - EE; }
    int pos = g_offs[d] + atomicAdd(&g_cursor[d], 1);
    g_csr_src[pos] = s;
}

// ------------------------------------------------------------------
// Per-node per-head attention coefficients (fp32)
// ------------------------------------------------------------------
__global__ void attn_coef_kernel(
    const float* __restrict__ hh, const float* __restrict__ asrc,
    const float* __restrict__ adst, float* __restrict__ es,
    float* __restrict__ ed, int H, int C)
{
    int node = blockIdx.x;
    int w = threadIdx.x >> 5, lane = threadIdx.x & 31;
    if (w >= H) return;
    const float* hrow = hh + (size_t)node * H * C + w * C;
    float s1 = 0.f, s2 = 0.f;
    for (int c = lane; c < C; c += 32) {
        float hv = hrow[c];
        s1 = fmaf(hv, asrc[w * C + c], s1);
        s2 = fmaf(hv, adst[w * C + c], s2);
    }
#pragma unroll
    for (int o = 16; o > 0; o >>= 1) {
        s1 += __shfl_xor_sync(0xffffffffu, s1, o);
        s2 += __shfl_xor_sync(0xffffffffu, s2, o);
    }
    if (lane == 0) { es[node * H + w] = s1; ed[node * H + w] = s2; }
}

// ------------------------------------------------------------------
// Segment softmax: one WARP per dst node. Writes NORMALIZED alpha.
// ------------------------------------------------------------------
template <int H>
__global__ __launch_bounds__(256) void softmax_kernel(
    const float* __restrict__ es, const float* __restrict__ ed,
    float* __restrict__ alpha)
{
    const int wid = threadIdx.x >> 5, lane = threadIdx.x & 31;
    const int d = blockIdx.x * 8 + wid;
    if (d >= NN) return;
    const int beg = g_offs[d];
    const int deg = g_offs[d + 1] - beg;

    float edv[H];
#pragma unroll
    for (int h = 0; h < H; h++) edv[h] = ed[d * H + h];

    float lm[H];
#pragma unroll
    for (int h = 0; h < H; h++) lm[h] = -FLT_MAX;
    for (int e = lane; e < deg; e += 32) {
        int s = g_csr_src[beg + e];
#pragma unroll
        for (int h = 0; h < H; h++)
            lm[h] = fmaxf(lm[h], lrelu02(es[s * H + h] + edv[h]));
    }
#pragma unroll
    for (int o = 16; o > 0; o >>= 1)
#pragma unroll
        for (int h = 0; h < H; h++)
            lm[h] = fmaxf(lm[h], __shfl_xor_sync(0xffffffffu, lm[h], o));

    float ls[H];
#pragma unroll
    for (int h = 0; h < H; h++) ls[h] = 0.f;
    for (int e = lane; e < deg; e += 32) {
        int s = g_csr_src[beg + e];
#pragma unroll
        for (int h = 0; h < H; h++) {
            float ex = expf(lrelu02(es[s * H + h] + edv[h]) - lm[h]);
            alpha[(size_t)(beg + e) * H + h] = ex;
            ls[h] += ex;
        }
    }
#pragma unroll
    for (int o = 16; o > 0; o >>= 1)
#pragma unroll
        for (int h = 0; h < H; h++)
            ls[h] += __shfl_xor_sync(0xffffffffu, ls[h], o);

    float inv[H];
#pragma unroll
    for (int h = 0; h < H; h++) inv[h] = 1.f / (ls[h] + 1e-16f);
    for (int e = lane; e < deg; e += 32) {
#pragma unroll
        for (int h = 0; h < H; h++)
            alpha[(size_t)(beg + e) * H + h] *= inv[h];
    }
}

// ------------------------------------------------------------------
// FUSED GAT tail: gather (fp32) + bias + LayerNorm + ELU (+ residual)
// + optional fp32 out + optional bf16 hi/lo split out.
// One block per dst node, T = H*C/4 threads, float4 per thread.
// LN math order identical to the old separate ln_elu kernel.
// ------------------------------------------------------------------
template <int H, int C>
__global__ __launch_bounds__(256) void gat_fused_kernel(
    const float* __restrict__ hh, const float* __restrict__ alpha,
    const float* __restrict__ bias, const float* __restrict__ gam,
    const float* __restrict__ bet, const float* __restrict__ resid,
    float* __restrict__ out,
    __nv_bfloat16* __restrict__ ohi, __nv_bfloat16* __restrict__ olo)
{
    const int HC = H * C;
    const int T = HC / 4;                 // blockDim.x
    const int d = blockIdx.x;
    const int tid = threadIdx.x;
    const int c = tid * 4;
    const int h = c / C;
    const int beg = g_offs[d];
    const int deg = g_offs[d + 1] - beg;

    // ---- gather ----
    float4 acc = make_float4(0.f, 0.f, 0.f, 0.f);
    for (int e = 0; e < deg; e++) {
        int s = g_csr_src[beg + e];
        float w = alpha[(size_t)(beg + e) * H + h];
        float4 v = *(const float4*)(hh + (size_t)s * HC + c);
        acc.x = fmaf(w, v.x, acc.x);
        acc.y = fmaf(w, v.y, acc.y);
        acc.z = fmaf(w, v.z, acc.z);
        acc.w = fmaf(w, v.w, acc.w);
    }

    // ---- bias + LN stats ----
    float v[4];
    v[0] = acc.x + bias[c + 0]; v[1] = acc.y + bias[c + 1];
    v[2] = acc.z + bias[c + 2]; v[3] = acc.w + bias[c + 3];
    __shared__ float r1[256], r2[256];
    r1[tid] = v[0] + v[1] + v[2] + v[3];
    r2[tid] = v[0]*v[0] + v[1]*v[1] + v[2]*v[2] + v[3]*v[3];
    __syncthreads();
    for (int o = T >> 1; o > 0; o >>= 1) {
        if (tid < o) { r1[tid] += r1[tid + o]; r2[tid] += r2[tid + o]; }
        __syncthreads();
    }
    float mu = r1[0] / (float)HC;
    float var = r2[0] / (float)HC - mu * mu;
    float rs = rsqrtf(var + 1e-5f);

    // ---- LN + ELU (+ residual) ----
    float y[4];
#pragma unroll
    for (int j = 0; j < 4; j++)
        y[j] = eluf((v[j] - mu) * rs * gam[c + j] + bet[c + j]);
    if (resid) {
        float4 r = *(const float4*)(resid + (size_t)d * HC + c);
        y[0] += r.x; y[1] += r.y; y[2] += r.z; y[3] += r.w;
    }

    if (out)
        *(float4*)(out + (size_t)d * HC + c) = make_float4(y[0], y[1], y[2], y[3]);
    if (ohi) {
        float h0 = bf16hi(y[0]), h1 = bf16hi(y[1]), h2 = bf16hi(y[2]), h3 = bf16hi(y[3]);
        uint2 hv, lv;
        hv.x = pack2(y[0], y[1]); hv.y = pack2(y[2], y[3]);
        lv.x = pack2(y[0] - h0, y[1] - h1); lv.y = pack2(y[2] - h2, y[3] - h3);
        *(uint2*)(ohi + (size_t)d * HC + c) = hv;
        *(uint2*)(olo + (size_t)d * HC + c) = lv;
    }
}

// ------------------------------------------------------------------
// Pooling + classifier
// ------------------------------------------------------------------
__device__ __forceinline__ void atomicMaxF(float* addr, float v) {
    if (v >= 0.f) atomicMax((int*)addr, __float_as_int(v));
    else          atomicMin((unsigned int*)addr, __float_as_uint(v));
}

__global__ void pool_init_kernel() {
    int i = blockIdx.x * blockDim.x + threadIdx.x;
    if (i < GG * 256) { g_ssum[i] = 0.f; g_smax[i] = -FLT_MAX; }
    if (i < GG) g_cnt[i] = 0;
}

__global__ void pool_acc_kernel(const int* __restrict__ batch) {
    int n = blockIdx.x, c = threadIdx.x;
    int g = batch[n];
    float v = g_x3[(size_t)n * 256 + c];
    atomicAdd(&g_ssum[g * 256 + c], v);
    atomicMaxF(&g_smax[g * 256 + c], v);
    if (c == 0) atomicAdd(&g_cnt[g], 1);
}

__global__ void pool_finalize_kernel() {
    int g = blockIdx.x, c = threadIdx.x;
    float s = g_ssum[g * 256 + c];
    float cn = (float)g_cnt[g];
    g_pooled[g * 768 + c]       = s / fmaxf(cn, 1.f);
    g_pooled[g * 768 + 256 + c] = g_smax[g * 256 + c];
    g_pooled[g * 768 + 512 + c] = s;
}

__global__ void cls_hidden_kernel(const float* __restrict__ w,
                                  const float* __restrict__ b) {
    int g = blockIdx.x, j = threadIdx.x;  // 128 threads
    const float* p = &g_pooled[g * 768];
    float s = 0.f;
    for (int k = 0; k < 768; k++) s = fmaf(p[k], w[k * 128 + j], s);
    s += b[j];
    g_hidden[g * 128 + j] = fmaxf(s, 0.f);
}

__global__ void cls_out_kernel(const float* __restrict__ w2,
                               const float* __restrict__ b2,
                               float* __restrict__ out) {
    int g = threadIdx.x;
    if (g < GG) {
        float s = 0.f;
        const float* hr = &g_hidden[g * 128];
        for (int k = 0; k < 128; k++) s = fmaf(hr[k], w2[k], s);
        out[g] = s + b2[0];
    }
}

// ------------------------------------------------------------------
// Host launcher
// ------------------------------------------------------------------
static void* symaddr(const void* s) {
    void* p = nullptr;
    cudaGetSymbolAddress(&p, s);
    return p;
}

static void prep_weights(const float* W, int K, int N, float* wt,
                         __nv_bfloat16* bhi, __nv_bfloat16* blo) {
    transpose_kernel<<<dim3(N / 32, K / 32), dim3(32, 8)>>>(W, wt, K, N);
    size_t tot = (size_t)N * K;
    split_kernel<<<(unsigned)((tot / 8 + 255) / 256), 256>>>(wt, bhi, blo, tot);
}

extern "C" void kernel_launch(void* const* d_in, const int* in_sizes, int n_in,
                              void* d_out, int out_size) {
    const float* x        = (const float*)d_in[0];
    const int*   ei       = (const int*)d_in[1];
    const int*   batch    = (const int*)d_in[2];
    const float* proj_w   = (const float*)d_in[3];
    const float* proj_b   = (const float*)d_in[4];
    const float* gat1_w   = (const float*)d_in[5];
    const float* att1_src = (const float*)d_in[6];
    const float* att1_dst = (const float*)d_in[7];
    const float* gat1_b   = (const float*)d_in[8];
    const float* ln1_g    = (const float*)d_in[9];
    const float* ln1_b    = (const float*)d_in[10];
    const float* gat2_w   = (const float*)d_in[11];
    const float* att2_src = (const float*)d_in[12];
    const float* att2_dst = (const float*)d_in[13];
    const float* gat2_b   = (const float*)d_in[14];
    const float* ln2_g    = (const float*)d_in[15];
    const float* ln2_b    = (const float*)d_in[16];
    const float* gat3_w   = (const float*)d_in[17];
    const float* att3_src = (const float*)d_in[18];
    const float* att3_dst = (const float*)d_in[19];
    const float* gat3_b   = (const float*)d_in[20];
    const float* ln3_g    = (const float*)d_in[21];
    const float* ln3_b    = (const float*)d_in[22];
    const float* cls1_w   = (const float*)d_in[23];
    const float* cls1_b   = (const float*)d_in[24];
    const float* cls2_w   = (const float*)d_in[25];
    const float* cls2_b   = (const float*)d_in[26];

    float* h0  = (float*)symaddr(g_h0);
    float* hh  = (float*)symaddr(g_hh);
    float* x1  = (float*)symaddr(g_x1);
    float* x3  = (float*)symaddr(g_x3);
    float* es  = (float*)symaddr(g_es);
    float* ed  = (float*)symaddr(g_ed);
    float* wt  = (float*)symaddr(g_wt);
    float* alpha = (float*)symaddr(g_alpha);
    __nv_bfloat16* ahi = (__nv_bfloat16*)symaddr(g_ahi);
    __nv_bfloat16* alo = (__nv_bfloat16*)symaddr(g_alo);
    __nv_bfloat16* bhi = (__nv_bfloat16*)symaddr(g_bhi);
    __nv_bfloat16* blo = (__nv_bfloat16*)symaddr(g_blo);
    int* counts = (int*)symaddr(g_counts);
    int* cursor = (int*)symaddr(g_cursor);

    cudaFuncSetAttribute(wmma_gemm_kernel,
                         cudaFuncAttributeMaxDynamicSharedMemorySize, GEMM_SMEM);

    const unsigned SM_GRID = (NN + 7) / 8;

    // ---- CSR build (shared by all layers) ----
    zero_int_kernel<<<(NN + 255) / 256, 256>>>(counts, NN);
    zero_int_kernel<<<(NN + 255) / 256, 256>>>(cursor, NN);
    count_kernel<<<(ET + 255) / 256, 256>>>(ei);
    scan_kernel<<<1, 1024>>>();
    fill_kernel<<<(ET + 255) / 256, 256>>>(ei);

    // ---- GEMM1: h0 = x @ proj_w (bias+elu fused into the split below) ----
    prep_weights(proj_w, 768, 768, wt, bhi, blo);
    {
        size_t tot = (size_t)NN * 768;
        split_kernel<<<(unsigned)((tot / 8 + 255) / 256), 256>>>(x, ahi, alo, tot);
    }
    wmma_gemm_kernel<<<dim3(768 / 128, NNP / 128), 256, GEMM_SMEM>>>(
        ahi, alo, bhi, blo, h0, 768, 768);
    bias_elu_split_kernel<<<(unsigned)(((size_t)NN * 768 / 8 + 255) / 256), 256>>>(
        h0, proj_b, ahi, alo, 768);

    // ---- GAT layer 1 ----
    prep_weights(gat1_w, 768, 1024, wt, bhi, blo);
    wmma_gemm_kernel<<<dim3(1024 / 128, NNP / 128), 256, GEMM_SMEM>>>(
        ahi, alo, bhi, blo, hh, 1024, 768);
    attn_coef_kernel<<<NN, 128>>>(hh, att1_src, att1_dst, es, ed, 4, 256);
    softmax_kernel<4><<<SM_GRID, 256>>>(es, ed, alpha);
    gat_fused_kernel<4, 256><<<NN, 256>>>(hh, alpha, gat1_b, ln1_g, ln1_b,
                                          nullptr, x1, ahi, alo);

    // ---- GAT layer 2 ----
    prep_weights(gat2_w, 1024, 1024, wt, bhi, blo);
    wmma_gemm_kernel<<<dim3(1024 / 128, NNP / 128), 256, GEMM_SMEM>>>(
        ahi, alo, bhi, blo, hh, 1024, 1024);
    attn_coef_kernel<<<NN, 128>>>(hh, att2_src, att2_dst, es, ed, 4, 256);
    softmax_kernel<4><<<SM_GRID, 256>>>(es, ed, alpha);
    // x2 fp32 never consumed -> only hi/lo split outputs (residual x1 inside)
    gat_fused_kernel<4, 256><<<NN, 256>>>(hh, alpha, gat2_b, ln2_g, ln2_b,
                                          x1, nullptr, ahi, alo);

    // ---- GAT layer 3 (1 head, 256 channels) ----
    prep_weights(gat3_w, 1024, 256, wt, bhi, blo);
    wmma_gemm_kernel<<<dim3(256 / 128, NNP / 128), 256, GEMM_SMEM>>>(
        ahi, alo, bhi, blo, hh, 256, 1024);
    attn_coef_kernel<<<NN, 32>>>(hh, att3_src, att3_dst, es, ed, 1, 256);
    softmax_kernel<1><<<SM_GRID, 256>>>(es, ed, alpha);
    gat_fused_kernel<1, 256><<<NN, 64>>>(hh, alpha, gat3_b, ln3_g, ln3_b,
                                         nullptr, x3, nullptr, nullptr);

    // ---- pooling ----
    pool_init_kernel<<<(GG * 256 + 255) / 256, 256>>>();
    pool_acc_kernel<<<NN, 256>>>(batch);
    pool_finalize_kernel<<<GG, 256>>>();

    // ---- classifier ----
    cls_hidden_kernel<<<GG, 128>>>(cls1_w, cls1_b);
    cls_out_kernel<<<1, 32>>>(cls2_w, cls2_b, (float*)d_out);
}

// round 14
// speedup vs baseline: 1.0801x; 1.0801x over previous
#include <cuda_runtime.h>
#include <cuda_bf16.h>
#include <mma.h>
#include <float.h>
#include <math.h>
#include <stdint.h>

using namespace nvcuda;

// Problem constants (fixed by the dataset)
#define NN 20000
#define NNP 20096          // 157 * 128 : M padded to a whole tile grid
#define EE 320000
#define ET (NN + EE)       // edges incl. self loops = 340000
#define GG 32

// ------------------------------------------------------------------
// Scratch (device globals; no runtime allocation allowed)
// ------------------------------------------------------------------
__device__ float g_h0[(size_t)NNP * 768];    // GEMM1 out (padded rows garbage, unread)
__device__ float g_hh[(size_t)NNP * 1024];   // GEMM2/3/4 out
__device__ float g_x1[NN * 1024];
__device__ float g_x3[NN * 256];
__device__ float g_es[NN * 4];
__device__ float g_ed[NN * 4];
__device__ float g_alpha[(size_t)ET * 4];
__device__ int   g_counts[NN];
__device__ int   g_offs[NN + 1];
__device__ int   g_cursor[NN];
__device__ int   g_csr_src[ET];
__device__ float g_ssum[GG * 256];
__device__ float g_smax[GG * 256];
__device__ int   g_cnt[GG];
__device__ float g_pooled[GG * 768];
__device__ float g_hidden[GG * 128];
__device__ float g_wt[1024 * 1024];                       // transposed weights (fp32)
__device__ __nv_bfloat16 g_ahi[(size_t)NNP * 1024];       // split A (hi)
__device__ __nv_bfloat16 g_alo[(size_t)NNP * 1024];       // split A (lo)
__device__ __nv_bfloat16 g_bhi[1024 * 1024];              // split Wt (hi)
__device__ __nv_bfloat16 g_blo[1024 * 1024];              // split Wt (lo)

__device__ __forceinline__ float lrelu02(float x) { return x > 0.f ? x : 0.2f * x; }
__device__ __forceinline__ float eluf(float x)    { return x > 0.f ? x : expm1f(x); }

__device__ __forceinline__ uint32_t smem_u32(const void* p) {
    uint32_t a;
    asm("{ .reg .u64 t; cvta.to.shared.u64 t, %1; cvt.u32.u64 %0, t; }" : "=r"(a) : "l"(p));
    return a;
}

// cp.async (Ampere-era PTX; compiles for plain sm_103)
#define CP_ASYNC16(dst_u32, src_ptr) \
    asm volatile("cp.async.cg.shared.global [%0], [%1], 16;" :: "r"(dst_u32), "l"(src_ptr))
#define CP_COMMIT() asm volatile("cp.async.commit_group;")
#define CP_WAIT1()  asm volatile("cp.async.wait_group 1;")
#define CP_WAIT0()  asm volatile("cp.async.wait_group 0;")

__device__ __forceinline__ uint32_t pack2(float x0, float x1) {
    __nv_bfloat162 h = __floats2bfloat162_rn(x0, x1);
    return *(uint32_t*)&h;
}
__device__ __forceinline__ float bf16hi(float x) {
    return __bfloat162float(__float2bfloat16_rn(x));
}

// ------------------------------------------------------------------
// 32x32 tiled transpose: Wt[N][K] = W[K][N]
// ------------------------------------------------------------------
__global__ void transpose_kernel(const float* __restrict__ W, float* __restrict__ Wt,
                                 int K, int N) {
    __shared__ float t[32][33];
    int n0 = blockIdx.x * 32, k0 = blockIdx.y * 32;
    for (int j = threadIdx.y; j < 32; j += 8)
        t[j][threadIdx.x] = W[(size_t)(k0 + j) * N + n0 + threadIdx.x];
    __syncthreads();
    for (int j = threadIdx.y; j < 32; j += 8)
        Wt[(size_t)(n0 + j) * K + k0 + threadIdx.x] = t[threadIdx.x][j];
}

// ------------------------------------------------------------------
// Split fp32 -> (hi, lo) bf16 arrays over total elements (8 per thread).
// ------------------------------------------------------------------
__global__ void split_kernel(const float* __restrict__ A,
                             __nv_bfloat16* __restrict__ hi,
                             __nv_bfloat16* __restrict__ lo,
                             size_t total) {
    size_t i8 = ((size_t)blockIdx.x * blockDim.x + threadIdx.x) * 8;
    if (i8 >= total) return;
    float4 a = *(const float4*)(A + i8);
    float4 b = *(const float4*)(A + i8 + 4);
    float h0 = bf16hi(a.x), h1 = bf16hi(a.y), h2 = bf16hi(a.z), h3 = bf16hi(a.w);
    float h4 = bf16hi(b.x), h5 = bf16hi(b.y), h6 = bf16hi(b.z), h7 = bf16hi(b.w);
    uint4 hv, lv;
    hv.x = pack2(a.x, a.y); hv.y = pack2(a.z, a.w);
    hv.z = pack2(b.x, b.y); hv.w = pack2(b.z, b.w);
    lv.x = pack2(a.x - h0, a.y - h1); lv.y = pack2(a.z - h2, a.w - h3);
    lv.z = pack2(b.x - h4, b.y - h5); lv.w = pack2(b.z - h6, b.w - h7);
    *(uint4*)(hi + i8) = hv;
    *(uint4*)(lo + i8) = lv;
}

// bias + ELU + split (GEMM1 epilogue; fp32 result is NOT kept)
__global__ void bias_elu_split_kernel(const float* __restrict__ h,
                                      const float* __restrict__ b,
                                      __nv_bfloat16* __restrict__ hi,
                                      __nv_bfloat16* __restrict__ lo, int D) {
    size_t i8 = ((size_t)blockIdx.x * blockDim.x + threadIdx.x) * 8;
    if (i8 >= (size_t)NN * D) return;
    int c0 = (int)(i8 % (size_t)D);
    float v[8];
#pragma unroll
    for (int j = 0; j < 8; j++) v[j] = eluf(h[i8 + j] + b[c0 + j]);
    uint4 hv, lv;
    float t0 = bf16hi(v[0]), t1 = bf16hi(v[1]), t2 = bf16hi(v[2]), t3 = bf16hi(v[3]);
    float t4 = bf16hi(v[4]), t5 = bf16hi(v[5]), t6 = bf16hi(v[6]), t7 = bf16hi(v[7]);
    hv.x = pack2(v[0], v[1]); hv.y = pack2(v[2], v[3]);
    hv.z = pack2(v[4], v[5]); hv.w = pack2(v[6], v[7]);
    lv.x = pack2(v[0] - t0, v[1] - t1); lv.y = pack2(v[2] - t2, v[3] - t3);
    lv.z = pack2(v[4] - t4, v[5] - t5); lv.w = pack2(v[6] - t6, v[7] - t7);
    *(uint4*)(hi + i8) = hv;
    *(uint4*)(lo + i8) = lv;
}

// ------------------------------------------------------------------
// WMMA split-bf16 GEMM (cp.async double-buffered).
// R14 change: __launch_bounds__(256, 2) forces regs <= 128 so TWO CTAs
// co-reside per SM (smem 2 x 80KB = 160KB <= 228KB), hiding the
// __syncthreads / cp.async bubbles of one CTA behind the other's HMMA.
// ------------------------------------------------------------------
#define PITCH 40
#define ARR_B (128 * PITCH * 2)
#define STAGE_B (4 * ARR_B)
#define GEMM_SMEM (2 * STAGE_B)

__global__ __launch_bounds__(256, 2) void wmma_gemm_kernel(
    const __nv_bfloat16* __restrict__ Ahi, const __nv_bfloat16* __restrict__ Alo,
    const __nv_bfloat16* __restrict__ Bhi, const __nv_bfloat16* __restrict__ Blo,
    float* __restrict__ C, int N, int K)
{
    extern __shared__ char smem[];
    const uint32_t sbase = smem_u32(smem);

    const int tid = threadIdx.x;
    const int wid = tid >> 5;
    const int bm = blockIdx.y * 128, bn = blockIdx.x * 128;
    const int wm = (wid >> 1) * 32, wn = (wid & 1) * 64;

    wmma::fragment<wmma::accumulator, 16, 16, 16, float> acc[2][4];
#pragma unroll
    for (int mt = 0; mt < 2; mt++)
#pragma unroll
        for (int nt = 0; nt < 4; nt++) wmma::fill_fragment(acc[mt][nt], 0.f);

    const int lr0 = tid >> 2;
    const int seg = (tid & 3) * 8;
    const __nv_bfloat16* gA[4] = {
        Ahi + (size_t)(bm + lr0) * K + seg, Alo + (size_t)(bm + lr0) * K + seg,
        Bhi + (size_t)(bn + lr0) * K + seg, Blo + (size_t)(bn + lr0) * K + seg };
    const size_t rowStride64 = (size_t)64 * K;
    const uint32_t dOff = (uint32_t)(lr0 * (PITCH * 2) + seg * 2);

    const int nch = K >> 5;

    {
#pragma unroll
        for (int a = 0; a < 4; a++) {
            uint32_t dst = sbase + a * ARR_B + dOff;
            CP_ASYNC16(dst, gA[a]);
            CP_ASYNC16(dst + 64 * (PITCH * 2), gA[a] + rowStride64);
        }
        CP_COMMIT();
    }

    for (int c = 0; c < nch; c++) {
        if (c + 1 < nch) {
            const int k0 = (c + 1) << 5;
            const uint32_t st = sbase + ((c + 1) & 1) * STAGE_B;
#pragma unroll
            for (int a = 0; a < 4; a++) {
                uint32_t dst = st + a * ARR_B + dOff;
                CP_ASYNC16(dst, gA[a] + k0);
                CP_ASYNC16(dst + 64 * (PITCH * 2), gA[a] + k0 + rowStride64);
            }
            CP_COMMIT();
            CP_WAIT1();
        } else {
            CP_WAIT0();
        }
        __syncthreads();

        const char* st = smem + (c & 1) * STAGE_B;
        const __nv_bfloat16* sAhi = (const __nv_bfloat16*)(st);
        const __nv_bfloat16* sAlo = (const __nv_bfloat16*)(st + ARR_B);
        const __nv_bfloat16* sBhi = (const __nv_bfloat16*)(st + 2 * ARR_B);
        const __nv_bfloat16* sBlo = (const __nv_bfloat16*)(st + 3 * ARR_B);

#pragma unroll
        for (int ks = 0; ks < 2; ks++) {
            wmma::fragment<wmma::matrix_a, 16, 16, 16, __nv_bfloat16, wmma::row_major> fahi[2], falo[2];
#pragma unroll
            for (int mt = 0; mt < 2; mt++) {
                wmma::load_matrix_sync(fahi[mt], sAhi + (wm + mt * 16) * PITCH + ks * 16, PITCH);
                wmma::load_matrix_sync(falo[mt], sAlo + (wm + mt * 16) * PITCH + ks * 16, PITCH);
            }
#pragma unroll
            for (int nt = 0; nt < 4; nt++) {
                wmma::fragment<wmma::matrix_b, 16, 16, 16, __nv_bfloat16, wmma::col_major> fbhi, fblo;
                wmma::load_matrix_sync(fbhi, sBhi + (wn + nt * 16) * PITCH + ks * 16, PITCH);
                wmma::load_matrix_sync(fblo, sBlo + (wn + nt * 16) * PITCH + ks * 16, PITCH);
#pragma unroll
                for (int mt = 0; mt < 2; mt++) {
                    wmma::mma_sync(acc[mt][nt], fahi[mt], fbhi, acc[mt][nt]);
                    wmma::mma_sync(acc[mt][nt], fahi[mt], fblo, acc[mt][nt]);
                    wmma::mma_sync(acc[mt][nt], falo[mt], fbhi, acc[mt][nt]);
                }
            }
        }
        __syncthreads();
    }

#pragma unroll
    for (int mt = 0; mt < 2; mt++)
#pragma unroll
        for (int nt = 0; nt < 4; nt++)
            wmma::store_matrix_sync(C + (size_t)(bm + wm + mt * 16) * N + bn + wn + nt * 16,
                                    acc[mt][nt], N, wmma::mem_row_major);
}

// ------------------------------------------------------------------
// CSR build (dst-grouped)
// ------------------------------------------------------------------
__global__ void zero2_kernel(int* p, int* q, int n) {
    int i = blockIdx.x * blockDim.x + threadIdx.x;
    if (i < n) { p[i] = 0; q[i] = 0; }
}

__global__ void count_kernel(const int* __restrict__ ei) {
    int e = blockIdx.x * blockDim.x + threadIdx.x;
    if (e >= ET) return;
    int d = (e < EE) ? ei[EE + e] : (e - EE);
    atomicAdd(&g_counts[d], 1);
}

__global__ void scan_kernel() {
    __shared__ int sums[1024];
    const int tid = threadIdx.x;
    const int CH = (NN + 1023) / 1024;
    int beg = tid * CH;
    int end = beg + CH; if (end > NN) end = NN;
    int s = 0;
    for (int i = beg; i < end; i++) s += g_counts[i];
    sums[tid] = s;
    __syncthreads();
    for (int o = 1; o < 1024; o <<= 1) {
        int v = (tid >= o) ? sums[tid - o] : 0;
        __syncthreads();
        sums[tid] += v;
        __syncthreads();
    }
    int run = (tid > 0) ? sums[tid - 1] : 0;
    for (int i = beg; i < end; i++) { g_offs[i] = run; run += g_counts[i]; }
    if (tid == 1023) g_offs[NN] = sums[1023];
}

__global__ void fill_kernel(const int* __restrict__ ei) {
    int e = blockIdx.x * blockDim.x + threadIdx.x;
    if (e >= ET) return;
    int s, d;
    if (e < EE) { s = ei[e]; d = ei[EE + e]; }
    else        { s = e - EE; d = e - EE; }
    int pos = g_offs[d] + atomicAdd(&g_cursor[d], 1);
    g_csr_src[pos] = s;
}

// ------------------------------------------------------------------
// Per-node per-head attention coefficients (fp32)
// ------------------------------------------------------------------
__global__ void attn_coef_kernel(
    const float* __restrict__ hh, const float* __restrict__ asrc,
    const float* __restrict__ adst, float* __restrict__ es,
    float* __restrict__ ed, int H, int C)
{
    int node = blockIdx.x;
    int w = threadIdx.x >> 5, lane = threadIdx.x & 31;
    if (w >= H) return;
    const float* hrow = hh + (size_t)node * H * C + w * C;
    float s1 = 0.f, s2 = 0.f;
    for (int c = lane; c < C; c += 32) {
        float hv = hrow[c];
        s1 = fmaf(hv, asrc[w * C + c], s1);
        s2 = fmaf(hv, adst[w * C + c], s2);
    }
#pragma unroll
    for (int o = 16; o > 0; o >>= 1) {
        s1 += __shfl_xor_sync(0xffffffffu, s1, o);
        s2 += __shfl_xor_sync(0xffffffffu, s2, o);
    }
    if (lane == 0) { es[node * H + w] = s1; ed[node * H + w] = s2; }
}

// ------------------------------------------------------------------
// Segment softmax: one WARP per dst node. Writes NORMALIZED alpha.
// ------------------------------------------------------------------
template <int H>
__global__ __launch_bounds__(256) void softmax_kernel(
    const float* __restrict__ es, const float* __restrict__ ed,
    float* __restrict__ alpha)
{
    const int wid = threadIdx.x >> 5, lane = threadIdx.x & 31;
    const int d = blockIdx.x * 8 + wid;
    if (d >= NN) return;
    const int beg = g_offs[d];
    const int deg = g_offs[d + 1] - beg;

    float edv[H];
#pragma unroll
    for (int h = 0; h < H; h++) edv[h] = ed[d * H + h];

    float lm[H];
#pragma unroll
    for (int h = 0; h < H; h++) lm[h] = -FLT_MAX;
    for (int e = lane; e < deg; e += 32) {
        int s = g_csr_src[beg + e];
#pragma unroll
        for (int h = 0; h < H; h++)
            lm[h] = fmaxf(lm[h], lrelu02(es[s * H + h] + edv[h]));
    }
#pragma unroll
    for (int o = 16; o > 0; o >>= 1)
#pragma unroll
        for (int h = 0; h < H; h++)
            lm[h] = fmaxf(lm[h], __shfl_xor_sync(0xffffffffu, lm[h], o));

    float ls[H];
#pragma unroll
    for (int h = 0; h < H; h++) ls[h] = 0.f;
    for (int e = lane; e < deg; e += 32) {
        int s = g_csr_src[beg + e];
#pragma unroll
        for (int h = 0; h < H; h++) {
            float ex = expf(lrelu02(es[s * H + h] + edv[h]) - lm[h]);
            alpha[(size_t)(beg + e) * H + h] = ex;
            ls[h] += ex;
        }
    }
#pragma unroll
    for (int o = 16; o > 0; o >>= 1)
#pragma unroll
        for (int h = 0; h < H; h++)
            ls[h] += __shfl_xor_sync(0xffffffffu, ls[h], o);

    float inv[H];
#pragma unroll
    for (int h = 0; h < H; h++) inv[h] = 1.f / (ls[h] + 1e-16f);
    for (int e = lane; e < deg; e += 32) {
#pragma unroll
        for (int h = 0; h < H; h++)
            alpha[(size_t)(beg + e) * H + h] *= inv[h];
    }
}

// ------------------------------------------------------------------
// FUSED GAT tail: gather (fp32) + bias + LayerNorm + ELU (+ residual)
// + optional fp32 out + optional bf16 hi/lo split out.
// One block per dst node, T = H*C/4 threads, float4 per thread.
// ------------------------------------------------------------------
template <int H, int C>
__global__ __launch_bounds__(256) void gat_fused_kernel(
    const float* __restrict__ hh, const float* __restrict__ alpha,
    const float* __restrict__ bias, const float* __restrict__ gam,
    const float* __restrict__ bet, const float* __restrict__ resid,
    float* __restrict__ out,
    __nv_bfloat16* __restrict__ ohi, __nv_bfloat16* __restrict__ olo)
{
    const int HC = H * C;
    const int T = HC / 4;                 // blockDim.x
    const int d = blockIdx.x;
    const int tid = threadIdx.x;
    const int c = tid * 4;
    const int h = c / C;
    const int beg = g_offs[d];
    const int deg = g_offs[d + 1] - beg;

    // ---- gather ----
    float4 acc = make_float4(0.f, 0.f, 0.f, 0.f);
    for (int e = 0; e < deg; e++) {
        int s = g_csr_src[beg + e];
        float w = alpha[(size_t)(beg + e) * H + h];
        float4 v = *(const float4*)(hh + (size_t)s * HC + c);
        acc.x = fmaf(w, v.x, acc.x);
        acc.y = fmaf(w, v.y, acc.y);
        acc.z = fmaf(w, v.z, acc.z);
        acc.w = fmaf(w, v.w, acc.w);
    }

    // ---- bias + LN stats ----
    float v[4];
    v[0] = acc.x + bias[c + 0]; v[1] = acc.y + bias[c + 1];
    v[2] = acc.z + bias[c + 2]; v[3] = acc.w + bias[c + 3];
    __shared__ float r1[256], r2[256];
    r1[tid] = v[0] + v[1] + v[2] + v[3];
    r2[tid] = v[0]*v[0] + v[1]*v[1] + v[2]*v[2] + v[3]*v[3];
    __syncthreads();
    for (int o = T >> 1; o > 0; o >>= 1) {
        if (tid < o) { r1[tid] += r1[tid + o]; r2[tid] += r2[tid + o]; }
        __syncthreads();
    }
    float mu = r1[0] / (float)HC;
    float var = r2[0] / (float)HC - mu * mu;
    float rs = rsqrtf(var + 1e-5f);

    // ---- LN + ELU (+ residual) ----
    float y[4];
#pragma unroll
    for (int j = 0; j < 4; j++)
        y[j] = eluf((v[j] - mu) * rs * gam[c + j] + bet[c + j]);
    if (resid) {
        float4 r = *(const float4*)(resid + (size_t)d * HC + c);
        y[0] += r.x; y[1] += r.y; y[2] += r.z; y[3] += r.w;
    }

    if (out)
        *(float4*)(out + (size_t)d * HC + c) = make_float4(y[0], y[1], y[2], y[3]);
    if (ohi) {
        float h0 = bf16hi(y[0]), h1 = bf16hi(y[1]), h2 = bf16hi(y[2]), h3 = bf16hi(y[3]);
        uint2 hv, lv;
        hv.x = pack2(y[0], y[1]); hv.y = pack2(y[2], y[3]);
        lv.x = pack2(y[0] - h0, y[1] - h1); lv.y = pack2(y[2] - h2, y[3] - h3);
        *(uint2*)(ohi + (size_t)d * HC + c) = hv;
        *(uint2*)(olo + (size_t)d * HC + c) = lv;
    }
}

// ------------------------------------------------------------------
// Pooling + classifier
// ------------------------------------------------------------------
__device__ __forceinline__ void atomicMaxF(float* addr, float v) {
    if (v >= 0.f) atomicMax((int*)addr, __float_as_int(v));
    else          atomicMin((unsigned int*)addr, __float_as_uint(v));
}

__global__ void pool_init_kernel() {
    int i = blockIdx.x * blockDim.x + threadIdx.x;
    if (i < GG * 256) { g_ssum[i] = 0.f; g_smax[i] = -FLT_MAX; }
    if (i < GG) g_cnt[i] = 0;
}

__global__ void pool_acc_kernel(const int* __restrict__ batch) {
    int n = blockIdx.x, c = threadIdx.x;
    int g = batch[n];
    float v = g_x3[(size_t)n * 256 + c];
    atomicAdd(&g_ssum[g * 256 + c], v);
    atomicMaxF(&g_smax[g * 256 + c], v);
    if (c == 0) atomicAdd(&g_cnt[g], 1);
}

__global__ void pool_finalize_kernel() {
    int g = blockIdx.x, c = threadIdx.x;
    float s = g_ssum[g * 256 + c];
    float cn = (float)g_cnt[g];
    g_pooled[g * 768 + c]       = s / fmaxf(cn, 1.f);
    g_pooled[g * 768 + 256 + c] = g_smax[g * 256 + c];
    g_pooled[g * 768 + 512 + c] = s;
}

__global__ void cls_hidden_kernel(const float* __restrict__ w,
                                  const float* __restrict__ b) {
    int g = blockIdx.x, j = threadIdx.x;  // 128 threads
    const float* p = &g_pooled[g * 768];
    float s = 0.f;
    for (int k = 0; k < 768; k++) s = fmaf(p[k], w[k * 128 + j], s);
    s += b[j];
    g_hidden[g * 128 + j] = fmaxf(s, 0.f);
}

__global__ void cls_out_kernel(const float* __restrict__ w2,
                               const float* __restrict__ b2,
                               float* __restrict__ out) {
    int g = threadIdx.x;
    if (g < GG) {
        float s = 0.f;
        const float* hr = &g_hidden[g * 128];
        for (int k = 0; k < 128; k++) s = fmaf(hr[k], w2[k], s);
        out[g] = s + b2[0];
    }
}

// ------------------------------------------------------------------
// Host launcher
// ------------------------------------------------------------------
static void* symaddr(const void* s) {
    void* p = nullptr;
    cudaGetSymbolAddress(&p, s);
    return p;
}

static void prep_weights(const float* W, int K, int N, float* wt,
                         __nv_bfloat16* bhi, __nv_bfloat16* blo) {
    transpose_kernel<<<dim3(N / 32, K / 32), dim3(32, 8)>>>(W, wt, K, N);
    size_t tot = (size_t)N * K;
    split_kernel<<<(unsigned)((tot / 8 + 255) / 256), 256>>>(wt, bhi, blo, tot);
}

extern "C" void kernel_launch(void* const* d_in, const int* in_sizes, int n_in,
                              void* d_out, int out_size) {
    const float* x        = (const float*)d_in[0];
    const int*   ei       = (const int*)d_in[1];
    const int*   batch    = (const int*)d_in[2];
    const float* proj_w   = (const float*)d_in[3];
    const float* proj_b   = (const float*)d_in[4];
    const float* gat1_w   = (const float*)d_in[5];
    const float* att1_src = (const float*)d_in[6];
    const float* att1_dst = (const float*)d_in[7];
    const float* gat1_b   = (const float*)d_in[8];
    const float* ln1_g    = (const float*)d_in[9];
    const float* ln1_b    = (const float*)d_in[10];
    const float* gat2_w   = (const float*)d_in[11];
    const float* att2_src = (const float*)d_in[12];
    const float* att2_dst = (const float*)d_in[13];
    const float* gat2_b   = (const float*)d_in[14];
    const float* ln2_g    = (const float*)d_in[15];
    const float* ln2_b    = (const float*)d_in[16];
    const float* gat3_w   = (const float*)d_in[17];
    const float* att3_src = (const float*)d_in[18];
    const float* att3_dst = (const float*)d_in[19];
    const float* gat3_b   = (const float*)d_in[20];
    const float* ln3_g    = (const float*)d_in[21];
    const float* ln3_b    = (const float*)d_in[22];
    const float* cls1_w   = (const float*)d_in[23];
    const float* cls1_b   = (const float*)d_in[24];
    const float* cls2_w   = (const float*)d_in[25];
    const float* cls2_b   = (const float*)d_in[26];

    float* h0  = (float*)symaddr(g_h0);
    float* hh  = (float*)symaddr(g_hh);
    float* x1  = (float*)symaddr(g_x1);
    float* x3  = (float*)symaddr(g_x3);
    float* es  = (float*)symaddr(g_es);
    float* ed  = (float*)symaddr(g_ed);
    float* wt  = (float*)symaddr(g_wt);
    float* alpha = (float*)symaddr(g_alpha);
    __nv_bfloat16* ahi = (__nv_bfloat16*)symaddr(g_ahi);
    __nv_bfloat16* alo = (__nv_bfloat16*)symaddr(g_alo);
    __nv_bfloat16* bhi = (__nv_bfloat16*)symaddr(g_bhi);
    __nv_bfloat16* blo = (__nv_bfloat16*)symaddr(g_blo);
    int* counts = (int*)symaddr(g_counts);
    int* cursor = (int*)symaddr(g_cursor);

    cudaFuncSetAttribute(wmma_gemm_kernel,
                         cudaFuncAttributeMaxDynamicSharedMemorySize, GEMM_SMEM);

    const unsigned SM_GRID = (NN + 7) / 8;

    // ---- CSR build (shared by all layers) ----
    zero2_kernel<<<(NN + 255) / 256, 256>>>(counts, cursor, NN);
    count_kernel<<<(ET + 255) / 256, 256>>>(ei);
    scan_kernel<<<1, 1024>>>();
    fill_kernel<<<(ET + 255) / 256, 256>>>(ei);

    // ---- GEMM1: h0 = x @ proj_w (bias+elu fused into the split below) ----
    prep_weights(proj_w, 768, 768, wt, bhi, blo);
    {
        size_t tot = (size_t)NN * 768;
        split_kernel<<<(unsigned)((tot / 8 + 255) / 256), 256>>>(x, ahi, alo, tot);
    }
    wmma_gemm_kernel<<<dim3(768 / 128, NNP / 128), 256, GEMM_SMEM>>>(
        ahi, alo, bhi, blo, h0, 768, 768);
    bias_elu_split_kernel<<<(unsigned)(((size_t)NN * 768 / 8 + 255) / 256), 256>>>(
        h0, proj_b, ahi, alo, 768);

    // ---- GAT layer 1 ----
    prep_weights(gat1_w, 768, 1024, wt, bhi, blo);
    wmma_gemm_kernel<<<dim3(1024 / 128, NNP / 128), 256, GEMM_SMEM>>>(
        ahi, alo, bhi, blo, hh, 1024, 768);
    attn_coef_kernel<<<NN, 128>>>(hh, att1_src, att1_dst, es, ed, 4, 256);
    softmax_kernel<4><<<SM_GRID, 256>>>(es, ed, alpha);
    gat_fused_kernel<4, 256><<<NN, 256>>>(hh, alpha, gat1_b, ln1_g, ln1_b,
                                          nullptr, x1, ahi, alo);

    // ---- GAT layer 2 ----
    prep_weights(gat2_w, 1024, 1024, wt, bhi, blo);
    wmma_gemm_kernel<<<dim3(1024 / 128, NNP / 128), 256, GEMM_SMEM>>>(
        ahi, alo, bhi, blo, hh, 1024, 1024);
    attn_coef_kernel<<<NN, 128>>>(hh, att2_src, att2_dst, es, ed, 4, 256);
    softmax_kernel<4><<<SM_GRID, 256>>>(es, ed, alpha);
    // x2 fp32 never consumed -> only hi/lo split outputs (residual x1 inside)
    gat_fused_kernel<4, 256><<<NN, 256>>>(hh, alpha, gat2_b, ln2_g, ln2_b,
                                          x1, nullptr, ahi, alo);

    // ---- GAT layer 3 (1 head, 256 channels) ----
    prep_weights(gat3_w, 1024, 256, wt, bhi, blo);
    wmma_gemm_kernel<<<dim3(256 / 128, NNP / 128), 256, GEMM_SMEM>>>(
        ahi, alo, bhi, blo, hh, 256, 1024);
    attn_coef_kernel<<<NN, 32>>>(hh, att3_src, att3_dst, es, ed, 1, 256);
    softmax_kernel<1><<<SM_GRID, 256>>>(es, ed, alpha);
    gat_fused_kernel<1, 256><<<NN, 64>>>(hh, alpha, gat3_b, ln3_g, ln3_b,
                                         nullptr, x3, nullptr, nullptr);

    // ---- pooling ----
    pool_init_kernel<<<(GG * 256 + 255) / 256, 256>>>();
    pool_acc_kernel<<<NN, 256>>>(batch);
    pool_finalize_kernel<<<GG, 256>>>();

    // ---- classifier ----
    cls_hidden_kernel<<<GG, 128>>>(cls1_w, cls1_b);
    cls_out_kernel<<<1, 32>>>(cls2_w, cls2_b, (float*)d_out);
}

// round 15
// speedup vs baseline: 1.1003x; 1.0187x over previous
#include <cuda_runtime.h>
#include <cuda_bf16.h>
#include <mma.h>
#include <float.h>
#include <math.h>
#include <stdint.h>

using namespace nvcuda;

// Problem constants (fixed by the dataset)
#define NN 20000
#define NNP 20096          // 157 * 128 : M padded to a whole tile grid
#define EE 320000
#define ET (NN + EE)       // edges incl. self loops = 340000
#define GG 32

// ------------------------------------------------------------------
// Scratch (device globals; no runtime allocation allowed)
// ------------------------------------------------------------------
__device__ float g_h0[(size_t)NNP * 768];    // GEMM1 out (padded rows garbage, unread)
__device__ float g_hh[(size_t)NNP * 1024];   // GEMM2/3/4 out
__device__ float g_x1[NN * 1024];
__device__ float g_x3[NN * 256];
__device__ float g_es[NN * 4];
__device__ float g_ed[NN * 4];
__device__ float g_alpha[(size_t)ET * 4];
__device__ int   g_counts[NN];
__device__ int   g_offs[NN + 1];
__device__ int   g_cursor[NN];
__device__ int   g_csr_src[ET];
__device__ float g_ssum[GG * 256];
__device__ float g_smax[GG * 256];
__device__ int   g_cnt[GG];
__device__ float g_pooled[GG * 768];
__device__ float g_hidden[GG * 128];
__device__ float g_wt[1024 * 1024];                       // transposed weights (fp32)
__device__ __nv_bfloat16 g_ahi[(size_t)NNP * 1024];       // split A (hi)
__device__ __nv_bfloat16 g_alo[(size_t)NNP * 1024];       // split A (lo)
__device__ __nv_bfloat16 g_bhi[1024 * 1024];              // split Wt (hi)
__device__ __nv_bfloat16 g_blo[1024 * 1024];              // split Wt (lo)

__device__ __forceinline__ float lrelu02(float x) { return x > 0.f ? x : 0.2f * x; }
__device__ __forceinline__ float eluf(float x)    { return x > 0.f ? x : expm1f(x); }

__device__ __forceinline__ uint32_t smem_u32(const void* p) {
    uint32_t a;
    asm("{ .reg .u64 t; cvta.to.shared.u64 t, %1; cvt.u32.u64 %0, t; }" : "=r"(a) : "l"(p));
    return a;
}

// cp.async (Ampere-era PTX; compiles for plain sm_103)
#define CP_ASYNC16(dst_u32, src_ptr) \
    asm volatile("cp.async.cg.shared.global [%0], [%1], 16;" :: "r"(dst_u32), "l"(src_ptr))
#define CP_COMMIT() asm volatile("cp.async.commit_group;")
#define CP_WAIT1()  asm volatile("cp.async.wait_group 1;")
#define CP_WAIT0()  asm volatile("cp.async.wait_group 0;")

__device__ __forceinline__ uint32_t pack2(float x0, float x1) {
    __nv_bfloat162 h = __floats2bfloat162_rn(x0, x1);
    return *(uint32_t*)&h;
}
__device__ __forceinline__ float bf16hi(float x) {
    return __bfloat162float(__float2bfloat16_rn(x));
}

// ------------------------------------------------------------------
// 32x32 tiled transpose: Wt[N][K] = W[K][N]
// ------------------------------------------------------------------
__global__ void transpose_kernel(const float* __restrict__ W, float* __restrict__ Wt,
                                 int K, int N) {
    __shared__ float t[32][33];
    int n0 = blockIdx.x * 32, k0 = blockIdx.y * 32;
    for (int j = threadIdx.y; j < 32; j += 8)
        t[j][threadIdx.x] = W[(size_t)(k0 + j) * N + n0 + threadIdx.x];
    __syncthreads();
    for (int j = threadIdx.y; j < 32; j += 8)
        Wt[(size_t)(n0 + j) * K + k0 + threadIdx.x] = t[threadIdx.x][j];
}

// ------------------------------------------------------------------
// Split fp32 -> (hi, lo) bf16 arrays over total elements (8 per thread).
// ------------------------------------------------------------------
__global__ void split_kernel(const float* __restrict__ A,
                             __nv_bfloat16* __restrict__ hi,
                             __nv_bfloat16* __restrict__ lo,
                             size_t total) {
    size_t i8 = ((size_t)blockIdx.x * blockDim.x + threadIdx.x) * 8;
    if (i8 >= total) return;
    float4 a = *(const float4*)(A + i8);
    float4 b = *(const float4*)(A + i8 + 4);
    float h0 = bf16hi(a.x), h1 = bf16hi(a.y), h2 = bf16hi(a.z), h3 = bf16hi(a.w);
    float h4 = bf16hi(b.x), h5 = bf16hi(b.y), h6 = bf16hi(b.z), h7 = bf16hi(b.w);
    uint4 hv, lv;
    hv.x = pack2(a.x, a.y); hv.y = pack2(a.z, a.w);
    hv.z = pack2(b.x, b.y); hv.w = pack2(b.z, b.w);
    lv.x = pack2(a.x - h0, a.y - h1); lv.y = pack2(a.z - h2, a.w - h3);
    lv.z = pack2(b.x - h4, b.y - h5); lv.w = pack2(b.z - h6, b.w - h7);
    *(uint4*)(hi + i8) = hv;
    *(uint4*)(lo + i8) = lv;
}

// bias + ELU + split (GEMM1 epilogue; fp32 result is NOT kept)
__global__ void bias_elu_split_kernel(const float* __restrict__ h,
                                      const float* __restrict__ b,
                                      __nv_bfloat16* __restrict__ hi,
                                      __nv_bfloat16* __restrict__ lo, int D) {
    size_t i8 = ((size_t)blockIdx.x * blockDim.x + threadIdx.x) * 8;
    if (i8 >= (size_t)NN * D) return;
    int c0 = (int)(i8 % (size_t)D);
    float v[8];
#pragma unroll
    for (int j = 0; j < 8; j++) v[j] = eluf(h[i8 + j] + b[c0 + j]);
    uint4 hv, lv;
    float t0 = bf16hi(v[0]), t1 = bf16hi(v[1]), t2 = bf16hi(v[2]), t3 = bf16hi(v[3]);
    float t4 = bf16hi(v[4]), t5 = bf16hi(v[5]), t6 = bf16hi(v[6]), t7 = bf16hi(v[7]);
    hv.x = pack2(v[0], v[1]); hv.y = pack2(v[2], v[3]);
    hv.z = pack2(v[4], v[5]); hv.w = pack2(v[6], v[7]);
    lv.x = pack2(v[0] - t0, v[1] - t1); lv.y = pack2(v[2] - t2, v[3] - t3);
    lv.z = pack2(v[4] - t4, v[5] - t5); lv.w = pack2(v[6] - t6, v[7] - t7);
    *(uint4*)(hi + i8) = hv;
    *(uint4*)(lo + i8) = lv;
}

// ------------------------------------------------------------------
// WMMA split-bf16 GEMM (cp.async double-buffered, 2 CTAs/SM) — validated.
// ------------------------------------------------------------------
#define PITCH 40
#define ARR_B (128 * PITCH * 2)
#define STAGE_B (4 * ARR_B)
#define GEMM_SMEM (2 * STAGE_B)

__global__ __launch_bounds__(256, 2) void wmma_gemm_kernel(
    const __nv_bfloat16* __restrict__ Ahi, const __nv_bfloat16* __restrict__ Alo,
    const __nv_bfloat16* __restrict__ Bhi, const __nv_bfloat16* __restrict__ Blo,
    float* __restrict__ C, int N, int K)
{
    extern __shared__ char smem[];
    const uint32_t sbase = smem_u32(smem);

    const int tid = threadIdx.x;
    const int wid = tid >> 5;
    const int bm = blockIdx.y * 128, bn = blockIdx.x * 128;
    const int wm = (wid >> 1) * 32, wn = (wid & 1) * 64;

    wmma::fragment<wmma::accumulator, 16, 16, 16, float> acc[2][4];
#pragma unroll
    for (int mt = 0; mt < 2; mt++)
#pragma unroll
        for (int nt = 0; nt < 4; nt++) wmma::fill_fragment(acc[mt][nt], 0.f);

    const int lr0 = tid >> 2;
    const int seg = (tid & 3) * 8;
    const __nv_bfloat16* gA[4] = {
        Ahi + (size_t)(bm + lr0) * K + seg, Alo + (size_t)(bm + lr0) * K + seg,
        Bhi + (size_t)(bn + lr0) * K + seg, Blo + (size_t)(bn + lr0) * K + seg };
    const size_t rowStride64 = (size_t)64 * K;
    const uint32_t dOff = (uint32_t)(lr0 * (PITCH * 2) + seg * 2);

    const int nch = K >> 5;

    {
#pragma unroll
        for (int a = 0; a < 4; a++) {
            uint32_t dst = sbase + a * ARR_B + dOff;
            CP_ASYNC16(dst, gA[a]);
            CP_ASYNC16(dst + 64 * (PITCH * 2), gA[a] + rowStride64);
        }
        CP_COMMIT();
    }

    for (int c = 0; c < nch; c++) {
        if (c + 1 < nch) {
            const int k0 = (c + 1) << 5;
            const uint32_t st = sbase + ((c + 1) & 1) * STAGE_B;
#pragma unroll
            for (int a = 0; a < 4; a++) {
                uint32_t dst = st + a * ARR_B + dOff;
                CP_ASYNC16(dst, gA[a] + k0);
                CP_ASYNC16(dst + 64 * (PITCH * 2), gA[a] + k0 + rowStride64);
            }
            CP_COMMIT();
            CP_WAIT1();
        } else {
            CP_WAIT0();
        }
        __syncthreads();

        const char* st = smem + (c & 1) * STAGE_B;
        const __nv_bfloat16* sAhi = (const __nv_bfloat16*)(st);
        const __nv_bfloat16* sAlo = (const __nv_bfloat16*)(st + ARR_B);
        const __nv_bfloat16* sBhi = (const __nv_bfloat16*)(st + 2 * ARR_B);
        const __nv_bfloat16* sBlo = (const __nv_bfloat16*)(st + 3 * ARR_B);

#pragma unroll
        for (int ks = 0; ks < 2; ks++) {
            wmma::fragment<wmma::matrix_a, 16, 16, 16, __nv_bfloat16, wmma::row_major> fahi[2], falo[2];
#pragma unroll
            for (int mt = 0; mt < 2; mt++) {
                wmma::load_matrix_sync(fahi[mt], sAhi + (wm + mt * 16) * PITCH + ks * 16, PITCH);
                wmma::load_matrix_sync(falo[mt], sAlo + (wm + mt * 16) * PITCH + ks * 16, PITCH);
            }
#pragma unroll
            for (int nt = 0; nt < 4; nt++) {
                wmma::fragment<wmma::matrix_b, 16, 16, 16, __nv_bfloat16, wmma::col_major> fbhi, fblo;
                wmma::load_matrix_sync(fbhi, sBhi + (wn + nt * 16) * PITCH + ks * 16, PITCH);
                wmma::load_matrix_sync(fblo, sBlo + (wn + nt * 16) * PITCH + ks * 16, PITCH);
#pragma unroll
                for (int mt = 0; mt < 2; mt++) {
                    wmma::mma_sync(acc[mt][nt], fahi[mt], fbhi, acc[mt][nt]);
                    wmma::mma_sync(acc[mt][nt], fahi[mt], fblo, acc[mt][nt]);
                    wmma::mma_sync(acc[mt][nt], falo[mt], fbhi, acc[mt][nt]);
                }
            }
        }
        __syncthreads();
    }

#pragma unroll
    for (int mt = 0; mt < 2; mt++)
#pragma unroll
        for (int nt = 0; nt < 4; nt++)
            wmma::store_matrix_sync(C + (size_t)(bm + wm + mt * 16) * N + bn + wn + nt * 16,
                                    acc[mt][nt], N, wmma::mem_row_major);
}

// ------------------------------------------------------------------
// CSR build (dst-grouped)
// ------------------------------------------------------------------
__global__ void zero2_kernel(int* p, int* q, int n) {
    int i = blockIdx.x * blockDim.x + threadIdx.x;
    if (i < n) { p[i] = 0; q[i] = 0; }
}

__global__ void count_kernel(const int* __restrict__ ei) {
    int e = blockIdx.x * blockDim.x + threadIdx.x;
    if (e >= ET) return;
    int d = (e < EE) ? ei[EE + e] : (e - EE);
    atomicAdd(&g_counts[d], 1);
}

__global__ void scan_kernel() {
    __shared__ int sums[1024];
    const int tid = threadIdx.x;
    const int CH = (NN + 1023) / 1024;
    int beg = tid * CH;
    int end = beg + CH; if (end > NN) end = NN;
    int s = 0;
    for (int i = beg; i < end; i++) s += g_counts[i];
    sums[tid] = s;
    __syncthreads();
    for (int o = 1; o < 1024; o <<= 1) {
        int v = (tid >= o) ? sums[tid - o] : 0;
        __syncthreads();
        sums[tid] += v;
        __syncthreads();
    }
    int run = (tid > 0) ? sums[tid - 1] : 0;
    for (int i = beg; i < end; i++) { g_offs[i] = run; run += g_counts[i]; }
    if (tid == 1023) g_offs[NN] = sums[1023];
}

__global__ void fill_kernel(const int* __restrict__ ei) {
    int e = blockIdx.x * blockDim.x + threadIdx.x;
    if (e >= ET) return;
    int s, d;
    if (e < EE) { s = ei[e]; d = ei[EE + e]; }
    else        { s = e - EE; d = e - EE; }
    int pos = g_offs[d] + atomicAdd(&g_cursor[d], 1);
    g_csr_src[pos] = s;
}

// ------------------------------------------------------------------
// Per-node per-head attention coefficients (fp32)
// ------------------------------------------------------------------
__global__ void attn_coef_kernel(
    const float* __restrict__ hh, const float* __restrict__ asrc,
    const float* __restrict__ adst, float* __restrict__ es,
    float* __restrict__ ed, int H, int C)
{
    int node = blockIdx.x;
    int w = threadIdx.x >> 5, lane = threadIdx.x & 31;
    if (w >= H) return;
    const float* hrow = hh + (size_t)node * H * C + w * C;
    float s1 = 0.f, s2 = 0.f;
    for (int c = lane; c < C; c += 32) {
        float hv = hrow[c];
        s1 = fmaf(hv, asrc[w * C + c], s1);
        s2 = fmaf(hv, adst[w * C + c], s2);
    }
#pragma unroll
    for (int o = 16; o > 0; o >>= 1) {
        s1 += __shfl_xor_sync(0xffffffffu, s1, o);
        s2 += __shfl_xor_sync(0xffffffffu, s2, o);
    }
    if (lane == 0) { es[node * H + w] = s1; ed[node * H + w] = s2; }
}

// ------------------------------------------------------------------
// Segment softmax: one WARP per dst node. Writes NORMALIZED alpha.
// ------------------------------------------------------------------
template <int H>
__global__ __launch_bounds__(256) void softmax_kernel(
    const float* __restrict__ es, const float* __restrict__ ed,
    float* __restrict__ alpha)
{
    const int wid = threadIdx.x >> 5, lane = threadIdx.x & 31;
    const int d = blockIdx.x * 8 + wid;
    if (d >= NN) return;
    const int beg = g_offs[d];
    const int deg = g_offs[d + 1] - beg;

    float edv[H];
#pragma unroll
    for (int h = 0; h < H; h++) edv[h] = ed[d * H + h];

    float lm[H];
#pragma unroll
    for (int h = 0; h < H; h++) lm[h] = -FLT_MAX;
    for (int e = lane; e < deg; e += 32) {
        int s = g_csr_src[beg + e];
#pragma unroll
        for (int h = 0; h < H; h++)
            lm[h] = fmaxf(lm[h], lrelu02(es[s * H + h] + edv[h]));
    }
#pragma unroll
    for (int o = 16; o > 0; o >>= 1)
#pragma unroll
        for (int h = 0; h < H; h++)
            lm[h] = fmaxf(lm[h], __shfl_xor_sync(0xffffffffu, lm[h], o));

    float ls[H];
#pragma unroll
    for (int h = 0; h < H; h++) ls[h] = 0.f;
    for (int e = lane; e < deg; e += 32) {
        int s = g_csr_src[beg + e];
#pragma unroll
        for (int h = 0; h < H; h++) {
            float ex = expf(lrelu02(es[s * H + h] + edv[h]) - lm[h]);
            alpha[(size_t)(beg + e) * H + h] = ex;
            ls[h] += ex;
        }
    }
#pragma unroll
    for (int o = 16; o > 0; o >>= 1)
#pragma unroll
        for (int h = 0; h < H; h++)
            ls[h] += __shfl_xor_sync(0xffffffffu, ls[h], o);

    float inv[H];
#pragma unroll
    for (int h = 0; h < H; h++) inv[h] = 1.f / (ls[h] + 1e-16f);
    for (int e = lane; e < deg; e += 32) {
#pragma unroll
        for (int h = 0; h < H; h++)
            alpha[(size_t)(beg + e) * H + h] *= inv[h];
    }
}

// ------------------------------------------------------------------
// FUSED GAT tail: gather (fp32) + bias + LayerNorm + ELU (+ residual)
// + optional fp32 out + optional bf16 hi/lo split out.
// R15: edge metadata (src index + alpha) staged through smem in chunks
// of 64 edges — removes the 2 redundant broadcast LDGs per thread per
// edge that dominated the gather's LSU issue bandwidth.
// One block per dst node, T = H*C/4 threads, float4 per thread.
// ------------------------------------------------------------------
#define ECHUNK 64
template <int H, int C>
__global__ __launch_bounds__(256) void gat_fused_kernel(
    const float* __restrict__ hh, const float* __restrict__ alpha,
    const float* __restrict__ bias, const float* __restrict__ gam,
    const float* __restrict__ bet, const float* __restrict__ resid,
    float* __restrict__ out,
    __nv_bfloat16* __restrict__ ohi, __nv_bfloat16* __restrict__ olo)
{
    const int HC = H * C;
    const int T = HC / 4;                 // blockDim.x
    const int d = blockIdx.x;
    const int tid = threadIdx.x;
    const int c = tid * 4;
    const int h = c / C;
    const int beg = g_offs[d];
    const int deg = g_offs[d + 1] - beg;

    __shared__ int   s_src[ECHUNK];
    __shared__ float s_w[ECHUNK * H];
    __shared__ float r1[256], r2[256];

    // ---- gather with smem-staged edge metadata ----
    float4 acc = make_float4(0.f, 0.f, 0.f, 0.f);
    for (int e0 = 0; e0 < deg; e0 += ECHUNK) {
        const int n = (deg - e0 < ECHUNK) ? (deg - e0) : ECHUNK;
        __syncthreads();
        if (tid < n) s_src[tid] = g_csr_src[beg + e0 + tid];
        for (int i = tid; i < n * H; i += T)
            s_w[i] = alpha[(size_t)(beg + e0) * H + i];
        __syncthreads();
        for (int e = 0; e < n; e++) {
            int s = s_src[e];
            float w = s_w[e * H + h];
            float4 v = *(const float4*)(hh + (size_t)s * HC + c);
            acc.x = fmaf(w, v.x, acc.x);
            acc.y = fmaf(w, v.y, acc.y);
            acc.z = fmaf(w, v.z, acc.z);
            acc.w = fmaf(w, v.w, acc.w);
        }
    }

    // ---- bias + LN stats ----
    float v[4];
    v[0] = acc.x + bias[c + 0]; v[1] = acc.y + bias[c + 1];
    v[2] = acc.z + bias[c + 2]; v[3] = acc.w + bias[c + 3];
    __syncthreads();   // protect s_w/r1 reuse ordering
    r1[tid] = v[0] + v[1] + v[2] + v[3];
    r2[tid] = v[0]*v[0] + v[1]*v[1] + v[2]*v[2] + v[3]*v[3];
    __syncthreads();
    for (int o = T >> 1; o > 0; o >>= 1) {
        if (tid < o) { r1[tid] += r1[tid + o]; r2[tid] += r2[tid + o]; }
        __syncthreads();
    }
    float mu = r1[0] / (float)HC;
    float var = r2[0] / (float)HC - mu * mu;
    float rs = rsqrtf(var + 1e-5f);

    // ---- LN + ELU (+ residual) ----
    float y[4];
#pragma unroll
    for (int j = 0; j < 4; j++)
        y[j] = eluf((v[j] - mu) * rs * gam[c + j] + bet[c + j]);
    if (resid) {
        float4 r = *(const float4*)(resid + (size_t)d * HC + c);
        y[0] += r.x; y[1] += r.y; y[2] += r.z; y[3] += r.w;
    }

    if (out)
        *(float4*)(out + (size_t)d * HC + c) = make_float4(y[0], y[1], y[2], y[3]);
    if (ohi) {
        float h0 = bf16hi(y[0]), h1 = bf16hi(y[1]), h2 = bf16hi(y[2]), h3 = bf16hi(y[3]);
        uint2 hv, lv;
        hv.x = pack2(y[0], y[1]); hv.y = pack2(y[2], y[3]);
        lv.x = pack2(y[0] - h0, y[1] - h1); lv.y = pack2(y[2] - h2, y[3] - h3);
        *(uint2*)(ohi + (size_t)d * HC + c) = hv;
        *(uint2*)(olo + (size_t)d * HC + c) = lv;
    }
}

// ------------------------------------------------------------------
// Pooling + classifier
// ------------------------------------------------------------------
__device__ __forceinline__ void atomicMaxF(float* addr, float v) {
    if (v >= 0.f) atomicMax((int*)addr, __float_as_int(v));
    else          atomicMin((unsigned int*)addr, __float_as_uint(v));
}

__global__ void pool_init_kernel() {
    int i = blockIdx.x * blockDim.x + threadIdx.x;
    if (i < GG * 256) { g_ssum[i] = 0.f; g_smax[i] = -FLT_MAX; }
    if (i < GG) g_cnt[i] = 0;
}

__global__ void pool_acc_kernel(const int* __restrict__ batch) {
    int n = blockIdx.x, c = threadIdx.x;
    int g = batch[n];
    float v = g_x3[(size_t)n * 256 + c];
    atomicAdd(&g_ssum[g * 256 + c], v);
    atomicMaxF(&g_smax[g * 256 + c], v);
    if (c == 0) atomicAdd(&g_cnt[g], 1);
}

__global__ void pool_finalize_kernel() {
    int g = blockIdx.x, c = threadIdx.x;
    float s = g_ssum[g * 256 + c];
    float cn = (float)g_cnt[g];
    g_pooled[g * 768 + c]       = s / fmaxf(cn, 1.f);
    g_pooled[g * 768 + 256 + c] = g_smax[g * 256 + c];
    g_pooled[g * 768 + 512 + c] = s;
}

__global__ void cls_hidden_kernel(const float* __restrict__ w,
                                  const float* __restrict__ b) {
    int g = blockIdx.x, j = threadIdx.x;  // 128 threads
    const float* p = &g_pooled[g * 768];
    float s = 0.f;
    for (int k = 0; k < 768; k++) s = fmaf(p[k], w[k * 128 + j], s);
    s += b[j];
    g_hidden[g * 128 + j] = fmaxf(s, 0.f);
}

__global__ void cls_out_kernel(const float* __restrict__ w2,
                               const float* __restrict__ b2,
                               float* __restrict__ out) {
    int g = threadIdx.x;
    if (g < GG) {
        float s = 0.f;
        const float* hr = &g_hidden[g * 128];
        for (int k = 0; k < 128; k++) s = fmaf(hr[k], w2[k], s);
        out[g] = s + b2[0];
    }
}

// ------------------------------------------------------------------
// Host launcher
// ------------------------------------------------------------------
static void* symaddr(const void* s) {
    void* p = nullptr;
    cudaGetSymbolAddress(&p, s);
    return p;
}

static void prep_weights(const float* W, int K, int N, float* wt,
                         __nv_bfloat16* bhi, __nv_bfloat16* blo) {
    transpose_kernel<<<dim3(N / 32, K / 32), dim3(32, 8)>>>(W, wt, K, N);
    size_t tot = (size_t)N * K;
    split_kernel<<<(unsigned)((tot / 8 + 255) / 256), 256>>>(wt, bhi, blo, tot);
}

extern "C" void kernel_launch(void* const* d_in, const int* in_sizes, int n_in,
                              void* d_out, int out_size) {
    const float* x        = (const float*)d_in[0];
    const int*   ei       = (const int*)d_in[1];
    const int*   batch    = (const int*)d_in[2];
    const float* proj_w   = (const float*)d_in[3];
    const float* proj_b   = (const float*)d_in[4];
    const float* gat1_w   = (const float*)d_in[5];
    const float* att1_src = (const float*)d_in[6];
    const float* att1_dst = (const float*)d_in[7];
    const float* gat1_b   = (const float*)d_in[8];
    const float* ln1_g    = (const float*)d_in[9];
    const float* ln1_b    = (const float*)d_in[10];
    const float* gat2_w   = (const float*)d_in[11];
    const float* att2_src = (const float*)d_in[12];
    const float* att2_dst = (const float*)d_in[13];
    const float* gat2_b   = (const float*)d_in[14];
    const float* ln2_g    = (const float*)d_in[15];
    const float* ln2_b    = (const float*)d_in[16];
    const float* gat3_w   = (const float*)d_in[17];
    const float* att3_src = (const float*)d_in[18];
    const float* att3_dst = (const float*)d_in[19];
    const float* gat3_b   = (const float*)d_in[20];
    const float* ln3_g    = (const float*)d_in[21];
    const float* ln3_b    = (const float*)d_in[22];
    const float* cls1_w   = (const float*)d_in[23];
    const float* cls1_b   = (const float*)d_in[24];
    const float* cls2_w   = (const float*)d_in[25];
    const float* cls2_b   = (const float*)d_in[26];

    float* h0  = (float*)symaddr(g_h0);
    float* hh  = (float*)symaddr(g_hh);
    float* x1  = (float*)symaddr(g_x1);
    float* x3  = (float*)symaddr(g_x3);
    float* es  = (float*)symaddr(g_es);
    float* ed  = (float*)symaddr(g_ed);
    float* wt  = (float*)symaddr(g_wt);
    float* alpha = (float*)symaddr(g_alpha);
    __nv_bfloat16* ahi = (__nv_bfloat16*)symaddr(g_ahi);
    __nv_bfloat16* alo = (__nv_bfloat16*)symaddr(g_alo);
    __nv_bfloat16* bhi = (__nv_bfloat16*)symaddr(g_bhi);
    __nv_bfloat16* blo = (__nv_bfloat16*)symaddr(g_blo);
    int* counts = (int*)symaddr(g_counts);
    int* cursor = (int*)symaddr(g_cursor);

    cudaFuncSetAttribute(wmma_gemm_kernel,
                         cudaFuncAttributeMaxDynamicSharedMemorySize, GEMM_SMEM);

    const unsigned SM_GRID = (NN + 7) / 8;

    // ---- CSR build (shared by all layers) ----
    zero2_kernel<<<(NN + 255) / 256, 256>>>(counts, cursor, NN);
    count_kernel<<<(ET + 255) / 256, 256>>>(ei);
    scan_kernel<<<1, 1024>>>();
    fill_kernel<<<(ET + 255) / 256, 256>>>(ei);

    // ---- GEMM1: h0 = x @ proj_w (bias+elu fused into the split below) ----
    prep_weights(proj_w, 768, 768, wt, bhi, blo);
    {
        size_t tot = (size_t)NN * 768;
        split_kernel<<<(unsigned)((tot / 8 + 255) / 256), 256>>>(x, ahi, alo, tot);
    }
    wmma_gemm_kernel<<<dim3(768 / 128, NNP / 128), 256, GEMM_SMEM>>>(
        ahi, alo, bhi, blo, h0, 768, 768);
    bias_elu_split_kernel<<<(unsigned)(((size_t)NN * 768 / 8 + 255) / 256), 256>>>(
        h0, proj_b, ahi, alo, 768);

    // ---- GAT layer 1 ----
    prep_weights(gat1_w, 768, 1024, wt, bhi, blo);
    wmma_gemm_kernel<<<dim3(1024 / 128, NNP / 128), 256, GEMM_SMEM>>>(
        ahi, alo, bhi, blo, hh, 1024, 768);
    attn_coef_kernel<<<NN, 128>>>(hh, att1_src, att1_dst, es, ed, 4, 256);
    softmax_kernel<4><<<SM_GRID, 256>>>(es, ed, alpha);
    gat_fused_kernel<4, 256><<<NN, 256>>>(hh, alpha, gat1_b, ln1_g, ln1_b,
                                          nullptr, x1, ahi, alo);

    // ---- GAT layer 2 ----
    prep_weights(gat2_w, 1024, 1024, wt, bhi, blo);
    wmma_gemm_kernel<<<dim3(1024 / 128, NNP / 128), 256, GEMM_SMEM>>>(
        ahi, alo, bhi, blo, hh, 1024, 1024);
    attn_coef_kernel<<<NN, 128>>>(hh, att2_src, att2_dst, es, ed, 4, 256);
    softmax_kernel<4><<<SM_GRID, 256>>>(es, ed, alpha);
    // x2 fp32 never consumed -> only hi/lo split outputs (residual x1 inside)
    gat_fused_kernel<4, 256><<<NN, 256>>>(hh, alpha, gat2_b, ln2_g, ln2_b,
                                          x1, nullptr, ahi, alo);

    // ---- GAT layer 3 (1 head, 256 channels) ----
    prep_weights(gat3_w, 1024, 256, wt, bhi, blo);
    wmma_gemm_kernel<<<dim3(256 / 128, NNP / 128), 256, GEMM_SMEM>>>(
        ahi, alo, bhi, blo, hh, 256, 1024);
    attn_coef_kernel<<<NN, 32>>>(hh, att3_src, att3_dst, es, ed, 1, 256);
    softmax_kernel<1><<<SM_GRID, 256>>>(es, ed, alpha);
    gat_fused_kernel<1, 256><<<NN, 64>>>(hh, alpha, gat3_b, ln3_g, ln3_b,
                                         nullptr, x3, nullptr, nullptr);

    // ---- pooling ----
    pool_init_kernel<<<(GG * 256 + 255) / 256, 256>>>();
    pool_acc_kernel<<<NN, 256>>>(batch);
    pool_finalize_kernel<<<GG, 256>>>();

    // ---- classifier ----
    cls_hidden_kernel<<<GG, 128>>>(cls1_w, cls1_b);
    cls_out_kernel<<<1, 32>>>(cls2_w, cls2_b, (float*)d_out);
}